// round 1
// baseline (speedup 1.0000x reference)
#include <cuda_runtime.h>
#include <math.h>

#define NTOK 8192
#define DDIM 1024
#define NEXP 32
#define HDIM 128
#define TOPK 4
#define CAP  8192        // worst-case tokens per expert
#define TT   64          // tokens per FFN tile
#define HPAD 132         // HDIM + 4 padding for smem

// ---------------- scratch (device globals: no allocation allowed) ----------
__device__ int   g_count[NEXP];
__device__ int   g_dest [NEXP * CAP];   // token*4 + slot  (unique partial row)
__device__ float g_gatew[NEXP * CAP];   // sigmoid gate weight
__device__ float g_partial[(size_t)NTOK * TOPK * DDIM]; // 134 MB partial rows

// ---------------- kernel 0: zero expert counters ---------------------------
__global__ void zero_counts_kernel() {
    if (threadIdx.x < NEXP) g_count[threadIdx.x] = 0;
}

// ---------------- kernel 1: gate GEMM + sigmoid + top-4 routing ------------
// one warp per token; x row cached in registers (32 floats/lane)
__global__ void gate_topk_kernel(const float* __restrict__ x,
                                 const float* __restrict__ W) {
    __shared__ float sg[4][NEXP];
    const int warp = threadIdx.x >> 5;
    const int lane = threadIdx.x & 31;
    const int t = blockIdx.x * 4 + warp;

    float xr[32];
    const float* xp = x + (size_t)t * DDIM;
    #pragma unroll
    for (int j = 0; j < 32; j++) xr[j] = xp[j * 32 + lane];

    for (int e = 0; e < NEXP; e++) {
        const float* w = W + e * DDIM;
        float s = 0.f;
        #pragma unroll
        for (int j = 0; j < 32; j++) s += xr[j] * w[j * 32 + lane];
        #pragma unroll
        for (int o = 16; o > 0; o >>= 1) s += __shfl_xor_sync(0xffffffffu, s, o);
        if (lane == 0) sg[warp][e] = s;
    }
    __syncwarp();

    if (lane == 0) {
        #pragma unroll
        for (int k = 0; k < TOPK; k++) {
            float best = -3.4e38f; int be = 0;
            for (int e = 0; e < NEXP; e++) {
                float v = sg[warp][e];
                if (v > best) { best = v; be = e; }
            }
            sg[warp][be] = -3.4e38f;
            float gv = 1.0f / (1.0f + expf(-best));
            int pos = atomicAdd(&g_count[be], 1);
            g_dest [be * CAP + pos] = t * TOPK + k;
            g_gatew[be * CAP + pos] = gv;
        }
    }
}

// ---------------- kernel 2: grouped expert FFN -----------------------------
// grid: (128 token-tiles, 32 experts), 256 threads as 16x16, 4x8 reg tile.
// phase1: H = relu(X_tile @ keys[e]) * gate  (acc in registers, staged to smem)
// phase2: partial[dest] = H @ values[e]      (plain STG.128, no atomics)
__global__ __launch_bounds__(256) void expert_ffn_kernel(
        const float* __restrict__ x,
        const float* __restrict__ keys,
        const float* __restrict__ values) {
    const int e     = blockIdx.y;
    const int cnt   = g_count[e];
    const int start = blockIdx.x * TT;
    if (start >= cnt) return;
    const int nt = min(TT, cnt - start);

    __shared__ int   s_dest[TT];
    __shared__ float s_gate[TT];
    // union of  {Xs[TT][33] (2112) + Ks[32][HDIM] (4096)}  and  Hs[TT][HPAD] (8448)
    __shared__ float sraw[TT * HPAD];
    float* Xs = sraw;                 // [TT][33]
    float* Ks = sraw + TT * 33;       // [32][HDIM]
    float* Hs = sraw;                 // [TT][HPAD]

    const int tid = threadIdx.x;
    const int tx = tid & 15;          // 0..15 -> 8 output cols
    const int ty = tid >> 4;          // 0..15 -> 4 token rows

    if (tid < TT) {
        if (tid < nt) {
            int idx = e * CAP + start + tid;
            s_dest[tid] = g_dest[idx];
            s_gate[tid] = g_gatew[idx];
        } else {
            s_dest[tid] = 0;
            s_gate[tid] = 0.f;
        }
    }
    __syncthreads();

    float acc[4][8] = {};
    const float* Ke = keys + (size_t)e * DDIM * HDIM;

    for (int dc = 0; dc < DDIM; dc += 32) {
        // stage X tile (gathered rows), zero-fill tail rows
        {
            int c = tid & 31, r0 = tid >> 5;
            #pragma unroll
            for (int k = 0; k < 8; k++) {
                int r = r0 + k * 8;
                float v = 0.f;
                if (r < nt) v = x[(size_t)(s_dest[r] >> 2) * DDIM + dc + c];
                Xs[r * 33 + c] = v;
            }
        }
        // stage K tile [32][128]
        #pragma unroll
        for (int k = 0; k < 16; k++) {
            int idx = tid + k * 256;
            Ks[idx] = Ke[(size_t)(dc + (idx >> 7)) * HDIM + (idx & 127)];
        }
        __syncthreads();

        #pragma unroll 8
        for (int d = 0; d < 32; d++) {
            float4 b0 = *(const float4*)(Ks + d * HDIM + tx * 8);
            float4 b1 = *(const float4*)(Ks + d * HDIM + tx * 8 + 4);
            #pragma unroll
            for (int i = 0; i < 4; i++) {
                float a = Xs[(ty * 4 + i) * 33 + d];
                acc[i][0] += a * b0.x; acc[i][1] += a * b0.y;
                acc[i][2] += a * b0.z; acc[i][3] += a * b0.w;
                acc[i][4] += a * b1.x; acc[i][5] += a * b1.y;
                acc[i][6] += a * b1.z; acc[i][7] += a * b1.w;
            }
        }
        __syncthreads();
    }

    // relu * gate, stage H to smem (reuses Xs/Ks space)
    #pragma unroll
    for (int i = 0; i < 4; i++) {
        int r = ty * 4 + i;
        float g = s_gate[r];
        #pragma unroll
        for (int j = 0; j < 8; j++)
            Hs[r * HPAD + tx * 8 + j] = fmaxf(acc[i][j], 0.f) * g;
    }
    __syncthreads();

    const float* Ve = values + (size_t)e * HDIM * DDIM;
    for (int oc = 0; oc < DDIM; oc += 128) {
        float a2[4][8] = {};
        const float* vb = Ve + oc + tx * 8;
        #pragma unroll 4
        for (int hh = 0; hh < HDIM; hh++) {
            float4 v0 = *(const float4*)(vb + (size_t)hh * DDIM);
            float4 v1 = *(const float4*)(vb + (size_t)hh * DDIM + 4);
            #pragma unroll
            for (int i = 0; i < 4; i++) {
                float a = Hs[(ty * 4 + i) * HPAD + hh];
                a2[i][0] += a * v0.x; a2[i][1] += a * v0.y;
                a2[i][2] += a * v0.z; a2[i][3] += a * v0.w;
                a2[i][4] += a * v1.x; a2[i][5] += a * v1.y;
                a2[i][6] += a * v1.z; a2[i][7] += a * v1.w;
            }
        }
        #pragma unroll
        for (int i = 0; i < 4; i++) {
            int r = ty * 4 + i;
            if (r < nt) {
                float* op = g_partial + (size_t)s_dest[r] * DDIM + oc + tx * 8;
                *(float4*)op       = make_float4(a2[i][0], a2[i][1], a2[i][2], a2[i][3]);
                *(float4*)(op + 4) = make_float4(a2[i][4], a2[i][5], a2[i][6], a2[i][7]);
            }
        }
    }
}

// ---------------- kernel 3: gather 4 partial rows per token ----------------
__global__ void gather_kernel(float* __restrict__ out) {
    int i = blockIdx.x * blockDim.x + threadIdx.x;   // float4 index: [NTOK][256]
    int n = i >> 8, c = i & 255;
    const float4* p = (const float4*)g_partial;
    size_t base = (size_t)n * 4 * 256 + c;
    float4 a = p[base], b = p[base + 256], d = p[base + 512], f = p[base + 768];
    float4 r;
    r.x = a.x + b.x + d.x + f.x;
    r.y = a.y + b.y + d.y + f.y;
    r.z = a.z + b.z + d.z + f.z;
    r.w = a.w + b.w + d.w + f.w;
    ((float4*)out)[i] = r;
}

// ---------------- launch ----------------------------------------------------
extern "C" void kernel_launch(void* const* d_in, const int* in_sizes, int n_in,
                              void* d_out, int out_size) {
    const float* x      = (const float*)d_in[0];
    const float* W      = (const float*)d_in[1];
    const float* keys   = (const float*)d_in[2];
    const float* values = (const float*)d_in[3];
    float* out = (float*)d_out;

    zero_counts_kernel<<<1, 32>>>();
    gate_topk_kernel<<<NTOK / 4, 128>>>(x, W);
    expert_ffn_kernel<<<dim3(NTOK / TT, NEXP), 256>>>(x, keys, values);
    gather_kernel<<<(NTOK * DDIM / 4) / 256, 256>>>(out);
}

// round 2
// speedup vs baseline: 1.0083x; 1.0083x over previous
#include <cuda_runtime.h>
#include <math.h>

#define NTOK 8192
#define DDIM 1024
#define NEXP 32
#define HDIM 128
#define TOPK 4
#define CAP  8192        // worst-case tokens per expert
#define TT   64          // tokens per FFN tile
#define HPAD 132         // HDIM + 4 padding for smem

// packed fp32x2 FMA (FFMA2) — only reachable via PTX on sm_103a
#define FMA2(c, a, b) asm("fma.rn.f32x2 %0, %1, %2, %0;" : "+l"(c) : "l"(a), "l"(b))
#define PACK2(dst, f) asm("mov.b64 %0, {%1, %1};" : "=l"(dst) : "r"(__float_as_uint(f)))

// ---------------- scratch (device globals: no allocation allowed) ----------
__device__ int   g_count[NEXP];
__device__ int   g_dest [NEXP * CAP];   // token*4 + slot  (unique partial row)
__device__ float g_gatew[NEXP * CAP];   // sigmoid gate weight
__device__ float g_partial[(size_t)NTOK * TOPK * DDIM]; // 134 MB partial rows

// ---------------- kernel 0: zero expert counters ---------------------------
__global__ void zero_counts_kernel() {
    if (threadIdx.x < NEXP) g_count[threadIdx.x] = 0;
}

// ---------------- kernel 1: gate GEMM + sigmoid + top-4 routing ------------
__global__ void gate_topk_kernel(const float* __restrict__ x,
                                 const float* __restrict__ W) {
    __shared__ float sg[4][NEXP];
    const int warp = threadIdx.x >> 5;
    const int lane = threadIdx.x & 31;
    const int t = blockIdx.x * 4 + warp;

    float xr[32];
    const float* xp = x + (size_t)t * DDIM;
    #pragma unroll
    for (int j = 0; j < 32; j++) xr[j] = xp[j * 32 + lane];

    for (int e = 0; e < NEXP; e++) {
        const float* w = W + e * DDIM;
        float s = 0.f;
        #pragma unroll
        for (int j = 0; j < 32; j++) s += xr[j] * w[j * 32 + lane];
        #pragma unroll
        for (int o = 16; o > 0; o >>= 1) s += __shfl_xor_sync(0xffffffffu, s, o);
        if (lane == 0) sg[warp][e] = s;
    }
    __syncwarp();

    if (lane == 0) {
        #pragma unroll
        for (int k = 0; k < TOPK; k++) {
            float best = -3.4e38f; int be = 0;
            for (int e = 0; e < NEXP; e++) {
                float v = sg[warp][e];
                if (v > best) { best = v; be = e; }
            }
            sg[warp][be] = -3.4e38f;
            float gv = 1.0f / (1.0f + expf(-best));
            int pos = atomicAdd(&g_count[be], 1);
            g_dest [be * CAP + pos] = t * TOPK + k;
            g_gatew[be * CAP + pos] = gv;
        }
    }
}

// ---------------- kernel 2: grouped expert FFN (FFMA2 version) -------------
// grid: (128 token-tiles, 32 experts), 256 threads as 16x16, 4x8 reg tile
// held as 4x4 packed f32x2 accumulators.
__global__ __launch_bounds__(256) void expert_ffn_kernel(
        const float* __restrict__ x,
        const float* __restrict__ keys,
        const float* __restrict__ values) {
    const int e     = blockIdx.y;
    const int cnt   = g_count[e];
    const int start = blockIdx.x * TT;
    if (start >= cnt) return;
    const int nt = min(TT, cnt - start);

    __shared__ int   s_dest[TT];
    __shared__ float s_gate[TT];
    // union of {Xs[TT][33] (2112) + Ks[32][HDIM] (4096)} and Hs[TT][HPAD] (8448)
    __shared__ float sraw[TT * HPAD];
    float* Xs = sraw;                 // [TT][33]
    float* Ks = sraw + TT * 33;       // [32][HDIM]
    float* Hs = sraw;                 // [TT][HPAD]

    const int tid = threadIdx.x;
    const int tx = tid & 15;          // 0..15 -> 8 output cols (4 f32x2 pairs)
    const int ty = tid >> 4;          // 0..15 -> 4 token rows

    if (tid < TT) {
        if (tid < nt) {
            int idx = e * CAP + start + tid;
            s_dest[tid] = g_dest[idx];
            s_gate[tid] = g_gatew[idx];
        } else {
            s_dest[tid] = 0;
            s_gate[tid] = 0.f;
        }
    }
    __syncthreads();

    unsigned long long acc[4][4] = {};   // 0ull == packed (+0.f, +0.f)
    const float* Ke = keys + (size_t)e * DDIM * HDIM;

    for (int dc = 0; dc < DDIM; dc += 32) {
        // stage X tile (gathered rows), zero-fill tail rows
        {
            int c = tid & 31, r0 = tid >> 5;
            #pragma unroll
            for (int k = 0; k < 8; k++) {
                int r = r0 + k * 8;
                float v = 0.f;
                if (r < nt) v = x[(size_t)(s_dest[r] >> 2) * DDIM + dc + c];
                Xs[r * 33 + c] = v;
            }
        }
        // stage K tile [32][128]
        #pragma unroll
        for (int k = 0; k < 16; k++) {
            int idx = tid + k * 256;
            Ks[idx] = Ke[(size_t)(dc + (idx >> 7)) * HDIM + (idx & 127)];
        }
        __syncthreads();

        #pragma unroll 8
        for (int d = 0; d < 32; d++) {
            const ulonglong2* kp =
                (const ulonglong2*)(Ks + d * HDIM + tx * 8);
            ulonglong2 b0 = kp[0];   // cols 0-3 as two f32x2
            ulonglong2 b1 = kp[1];   // cols 4-7
            #pragma unroll
            for (int i = 0; i < 4; i++) {
                float a = Xs[(ty * 4 + i) * 33 + d];
                unsigned long long aa; PACK2(aa, a);
                FMA2(acc[i][0], aa, b0.x);
                FMA2(acc[i][1], aa, b0.y);
                FMA2(acc[i][2], aa, b1.x);
                FMA2(acc[i][3], aa, b1.y);
            }
        }
        __syncthreads();
    }

    // relu * gate, stage H to smem (reuses Xs/Ks space)
    #pragma unroll
    for (int i = 0; i < 4; i++) {
        int r = ty * 4 + i;
        float g = s_gate[r];
        #pragma unroll
        for (int j = 0; j < 4; j++) {
            unsigned int lo, hi;
            asm("mov.b64 {%0, %1}, %2;" : "=r"(lo), "=r"(hi) : "l"(acc[i][j]));
            Hs[r * HPAD + tx * 8 + j * 2]     = fmaxf(__uint_as_float(lo), 0.f) * g;
            Hs[r * HPAD + tx * 8 + j * 2 + 1] = fmaxf(__uint_as_float(hi), 0.f) * g;
        }
    }
    __syncthreads();

    const float* Ve = values + (size_t)e * HDIM * DDIM;
    for (int oc = 0; oc < DDIM; oc += 128) {
        unsigned long long a2[4][4] = {};
        const float* vb = Ve + oc + tx * 8;
        #pragma unroll 4
        for (int hh = 0; hh < HDIM; hh++) {
            const ulonglong2* vp = (const ulonglong2*)(vb + (size_t)hh * DDIM);
            ulonglong2 v0 = vp[0];
            ulonglong2 v1 = vp[1];
            #pragma unroll
            for (int i = 0; i < 4; i++) {
                float a = Hs[(ty * 4 + i) * HPAD + hh];
                unsigned long long aa; PACK2(aa, a);
                FMA2(a2[i][0], aa, v0.x);
                FMA2(a2[i][1], aa, v0.y);
                FMA2(a2[i][2], aa, v1.x);
                FMA2(a2[i][3], aa, v1.y);
            }
        }
        #pragma unroll
        for (int i = 0; i < 4; i++) {
            int r = ty * 4 + i;
            if (r < nt) {
                float* op = g_partial + (size_t)s_dest[r] * DDIM + oc + tx * 8;
                *(ulonglong2*)op       = make_ulonglong2(a2[i][0], a2[i][1]);
                *(ulonglong2*)(op + 4) = make_ulonglong2(a2[i][2], a2[i][3]);
            }
        }
    }
}

// ---------------- kernel 3: gather 4 partial rows per token ----------------
__global__ void gather_kernel(float* __restrict__ out) {
    int i = blockIdx.x * blockDim.x + threadIdx.x;   // float4 index: [NTOK][256]
    int n = i >> 8, c = i & 255;
    const float4* p = (const float4*)g_partial;
    size_t base = (size_t)n * 4 * 256 + c;
    float4 a = p[base], b = p[base + 256], d = p[base + 512], f = p[base + 768];
    float4 r;
    r.x = a.x + b.x + d.x + f.x;
    r.y = a.y + b.y + d.y + f.y;
    r.z = a.z + b.z + d.z + f.z;
    r.w = a.w + b.w + d.w + f.w;
    ((float4*)out)[i] = r;
}

// ---------------- launch ----------------------------------------------------
extern "C" void kernel_launch(void* const* d_in, const int* in_sizes, int n_in,
                              void* d_out, int out_size) {
    const float* x      = (const float*)d_in[0];
    const float* W      = (const float*)d_in[1];
    const float* keys   = (const float*)d_in[2];
    const float* values = (const float*)d_in[3];
    float* out = (float*)d_out;

    zero_counts_kernel<<<1, 32>>>();
    gate_topk_kernel<<<NTOK / 4, 128>>>(x, W);
    expert_ffn_kernel<<<dim3(NTOK / TT, NEXP), 256>>>(x, keys, values);
    gather_kernel<<<(NTOK * DDIM / 4) / 256, 256>>>(out);
}

// round 4
// speedup vs baseline: 2.5643x; 2.5433x over previous
#include <cuda_runtime.h>
#include <cuda_bf16.h>
#include <math.h>
#include <stdint.h>

#define NTOK 8192
#define DDIM 1024
#define NEXP 32
#define HDIM 128
#define TOPK 4
#define CAP  8192
#define MT   128          // tokens per FFN tile

// ---------------------------------------------------------------- helpers
__device__ __forceinline__ uint32_t smem_u32(const void* p) {
    uint32_t a;
    asm("{ .reg .u64 t; cvta.to.shared.u64 t, %1; cvt.u32.u64 %0, t; }" : "=r"(a) : "l"(p));
    return a;
}
__device__ __forceinline__ void ldsm_x4(uint32_t* r, uint32_t addr) {
    asm volatile("ldmatrix.sync.aligned.m8n8.x4.shared.b16 {%0,%1,%2,%3}, [%4];"
                 : "=r"(r[0]), "=r"(r[1]), "=r"(r[2]), "=r"(r[3]) : "r"(addr));
}
__device__ __forceinline__ void ldsm_x2(uint32_t* r, uint32_t addr) {
    asm volatile("ldmatrix.sync.aligned.m8n8.x2.shared.b16 {%0,%1}, [%2];"
                 : "=r"(r[0]), "=r"(r[1]) : "r"(addr));
}
__device__ __forceinline__ void mma_bf16(float* c, const uint32_t* a, const uint32_t* b) {
    asm volatile(
        "mma.sync.aligned.m16n8k16.row.col.f32.bf16.bf16.f32 "
        "{%0,%1,%2,%3},{%4,%5,%6,%7},{%8,%9},{%0,%1,%2,%3};"
        : "+f"(c[0]), "+f"(c[1]), "+f"(c[2]), "+f"(c[3])
        : "r"(a[0]), "r"(a[1]), "r"(a[2]), "r"(a[3]), "r"(b[0]), "r"(b[1]));
}
__device__ __forceinline__ void split_bf16(float v, __nv_bfloat16& h, __nv_bfloat16& l) {
    h = __float2bfloat16(v);
    l = __float2bfloat16(v - __bfloat162float(h));
}
__device__ __forceinline__ uint32_t pack_bf16(__nv_bfloat16 a, __nv_bfloat16 b) {
    return (uint32_t)__bfloat16_as_ushort(a) | ((uint32_t)__bfloat16_as_ushort(b) << 16);
}

// ---------------------------------------------------------------- scratch
__device__ int   g_count[NEXP];
__device__ int   g_dest [NEXP * CAP];
__device__ float g_gatew[NEXP * CAP];
__device__ float g_partial[(size_t)NTOK * TOPK * DDIM];
__device__ __nv_bfloat16 g_xhi[(size_t)NTOK * DDIM];
__device__ __nv_bfloat16 g_xlo[(size_t)NTOK * DDIM];
__device__ __nv_bfloat16 g_kth[(size_t)NEXP * HDIM * DDIM];  // keys^T [E][H][D]
__device__ __nv_bfloat16 g_ktl[(size_t)NEXP * HDIM * DDIM];
__device__ __nv_bfloat16 g_vth[(size_t)NEXP * DDIM * HDIM];  // values^T [E][D][H]
__device__ __nv_bfloat16 g_vtl[(size_t)NEXP * DDIM * HDIM];

// ---------------- kernel 0: zero counters ----------------------------------
__global__ void zero_counts_kernel() {
    if (threadIdx.x < NEXP) g_count[threadIdx.x] = 0;
}

// ---------------- kernel 1: gate GEMM + sigmoid + top-4 --------------------
__global__ void gate_topk_kernel(const float* __restrict__ x,
                                 const float* __restrict__ W) {
    __shared__ float sg[4][NEXP];
    const int warp = threadIdx.x >> 5, lane = threadIdx.x & 31;
    const int t = blockIdx.x * 4 + warp;
    float xr[32];
    const float* xp = x + (size_t)t * DDIM;
    #pragma unroll
    for (int j = 0; j < 32; j++) xr[j] = xp[j * 32 + lane];
    for (int e = 0; e < NEXP; e++) {
        const float* w = W + e * DDIM;
        float s = 0.f;
        #pragma unroll
        for (int j = 0; j < 32; j++) s += xr[j] * w[j * 32 + lane];
        #pragma unroll
        for (int o = 16; o > 0; o >>= 1) s += __shfl_xor_sync(0xffffffffu, s, o);
        if (lane == 0) sg[warp][e] = s;
    }
    __syncwarp();
    if (lane == 0) {
        #pragma unroll
        for (int k = 0; k < TOPK; k++) {
            float best = -3.4e38f; int be = 0;
            for (int e = 0; e < NEXP; e++) { float v = sg[warp][e]; if (v > best) { best = v; be = e; } }
            sg[warp][be] = -3.4e38f;
            float gv = 1.0f / (1.0f + expf(-best));
            int pos = atomicAdd(&g_count[be], 1);
            g_dest [be * CAP + pos] = t * TOPK + k;
            g_gatew[be * CAP + pos] = gv;
        }
    }
}

// ---------------- kernel 2: X -> bf16 hi/lo --------------------------------
__global__ void xcvt_kernel(const float* __restrict__ x) {
    size_t i = ((size_t)blockIdx.x * blockDim.x + threadIdx.x) * 8;
    float4 a = *(const float4*)(x + i), b = *(const float4*)(x + i + 4);
    __nv_bfloat16 h[8], l[8];
    split_bf16(a.x, h[0], l[0]); split_bf16(a.y, h[1], l[1]);
    split_bf16(a.z, h[2], l[2]); split_bf16(a.w, h[3], l[3]);
    split_bf16(b.x, h[4], l[4]); split_bf16(b.y, h[5], l[5]);
    split_bf16(b.z, h[6], l[6]); split_bf16(b.w, h[7], l[7]);
    *(uint4*)(g_xhi + i) = *(uint4*)h;
    *(uint4*)(g_xlo + i) = *(uint4*)l;
}

// ---------------- kernel 3: keys [E][D][H] -> keys^T [E][H][D] hi/lo -------
__global__ void keysT_kernel(const float* __restrict__ keys) {
    __shared__ float tile[32][33];
    int e = blockIdx.z, d0 = blockIdx.x * 32, h0 = blockIdx.y * 32;
    int tx = threadIdx.x, ty = threadIdx.y;
    const float* src = keys + (size_t)e * DDIM * HDIM;
    #pragma unroll
    for (int i = 0; i < 4; i++)
        tile[ty + i * 8][tx] = src[(size_t)(d0 + ty + i * 8) * HDIM + h0 + tx];
    __syncthreads();
    #pragma unroll
    for (int i = 0; i < 4; i++) {
        float v = tile[tx][ty + i * 8];
        __nv_bfloat16 h, l; split_bf16(v, h, l);
        size_t o = ((size_t)e * HDIM + h0 + ty + i * 8) * DDIM + d0 + tx;
        g_kth[o] = h; g_ktl[o] = l;
    }
}

// ---------------- kernel 4: values [E][H][D] -> values^T [E][D][H] hi/lo ---
__global__ void valsT_kernel(const float* __restrict__ values) {
    __shared__ float tile[32][33];
    int e = blockIdx.z, h0 = blockIdx.x * 32, d0 = blockIdx.y * 32;
    int tx = threadIdx.x, ty = threadIdx.y;
    const float* src = values + (size_t)e * HDIM * DDIM;
    #pragma unroll
    for (int i = 0; i < 4; i++)
        tile[ty + i * 8][tx] = src[(size_t)(h0 + ty + i * 8) * DDIM + d0 + tx];
    __syncthreads();
    #pragma unroll
    for (int i = 0; i < 4; i++) {
        float v = tile[tx][ty + i * 8];
        __nv_bfloat16 h, l; split_bf16(v, h, l);
        size_t o = ((size_t)e * DDIM + d0 + ty + i * 8) * HDIM + h0 + tx;
        g_vth[o] = h; g_vtl[o] = l;
    }
}

// ---------------- kernel 5: grouped FFN via mma.sync bf16 ------------------
// smem arena (dynamic):
//   0     s_dest[128] | 512 s_gate[128]
//   1024  arena (139264 B):
//     GEMM1 phase: A1hi@0 A1lo@18432 B1hi@36864 B1lo@55296   (stride 144, 64-el chunks)
//     GEMM2 phase: Hhi@0 Hlo@34816 B2hi@69632 B2lo@104448    (stride 272, 128-el rows)
#define SM_DEST  0
#define SM_GATE  512
#define SM_ARENA 1024
#define A1_HI 0
#define A1_LO 18432
#define B1_HI 36864
#define B1_LO 55296
#define H_HI  0
#define H_LO  34816
#define B2_HI 69632
#define B2_LO 104448
#define SM_TOTAL (1024 + 139264)

__global__ __launch_bounds__(256, 1) void moe_ffn_mma() {
    extern __shared__ char smc[];
    const uint32_t smb = smem_u32(smc);
    const int e = blockIdx.y;
    const int cnt = g_count[e];
    const int start = blockIdx.x * MT;
    if (start >= cnt) return;
    const int ntok = min(MT, cnt - start);

    const int tid = threadIdx.x, lane = tid & 31, wid = tid >> 5;
    const int m0 = (wid & 3) * 32;     // warp M offset (4 warps x 32)
    const int n0 = (wid >> 2) * 64;    // warp N offset (2 warps x 64)

    int*   s_dest = (int*)(smc + SM_DEST);
    float* s_gate = (float*)(smc + SM_GATE);
    if (tid < MT) {
        if (tid < ntok) {
            int idx = e * CAP + start + tid;
            s_dest[tid] = g_dest[idx];
            s_gate[tid] = g_gatew[idx];
        } else { s_dest[tid] = 0; s_gate[tid] = 0.f; }
    }
    __syncthreads();

    // ldmatrix lane address components
    const int rowo = (lane & 7) + ((lane >> 3) & 1) * 8;   // x4: row within 16
    const int colx = (lane >> 4) * 8;                      // x4: k half
    const int brow = lane & 7;                             // x2: row within 8
    const int bcol = ((lane >> 3) & 1) * 8;                // x2: k half

    float acc[2][8][4] = {};

    // ================= GEMM1: C1 = X @ keys^T (3-pass split) ===============
    for (int kc = 0; kc < DDIM / 64; kc++) {
        {   // stage A (gathered token rows) + B (keys^T rows), 64-el chunks
            int r = tid >> 1, hf = tid & 1;
            uint4 ah4[4], al4[4];
            if (r < ntok) {
                size_t so = (size_t)(s_dest[r] >> 2) * DDIM + kc * 64 + hf * 32;
                #pragma unroll
                for (int j = 0; j < 4; j++) {
                    ah4[j] = ((const uint4*)(g_xhi + so))[j];
                    al4[j] = ((const uint4*)(g_xlo + so))[j];
                }
            } else {
                #pragma unroll
                for (int j = 0; j < 4; j++) ah4[j] = al4[j] = make_uint4(0, 0, 0, 0);
            }
            size_t sb = ((size_t)e * HDIM + r) * DDIM + kc * 64 + hf * 32;
            #pragma unroll
            for (int j = 0; j < 4; j++) {
                uint32_t off = (uint32_t)r * 144 + hf * 64 + j * 16;
                *(uint4*)(smc + SM_ARENA + A1_HI + off) = ah4[j];
                *(uint4*)(smc + SM_ARENA + A1_LO + off) = al4[j];
                *(uint4*)(smc + SM_ARENA + B1_HI + off) = ((const uint4*)(g_kth + sb))[j];
                *(uint4*)(smc + SM_ARENA + B1_LO + off) = ((const uint4*)(g_ktl + sb))[j];
            }
        }
        __syncthreads();

        #pragma unroll
        for (int ks = 0; ks < 4; ks++) {
            const int kloc = ks * 16;
            uint32_t ah[2][4], al[2][4];
            #pragma unroll
            for (int mt2 = 0; mt2 < 2; mt2++) {
                uint32_t ao = (uint32_t)(m0 + mt2 * 16 + rowo) * 144 + (kloc + colx) * 2;
                ldsm_x4(ah[mt2], smb + SM_ARENA + A1_HI + ao);
                ldsm_x4(al[mt2], smb + SM_ARENA + A1_LO + ao);
            }
            #pragma unroll
            for (int nt2 = 0; nt2 < 8; nt2++) {
                uint32_t bo = (uint32_t)(n0 + nt2 * 8 + brow) * 144 + (kloc + bcol) * 2;
                uint32_t bh[2], bl[2];
                ldsm_x2(bh, smb + SM_ARENA + B1_HI + bo);
                ldsm_x2(bl, smb + SM_ARENA + B1_LO + bo);
                #pragma unroll
                for (int mt2 = 0; mt2 < 2; mt2++) {
                    mma_bf16(acc[mt2][nt2], ah[mt2], bh);
                    mma_bf16(acc[mt2][nt2], ah[mt2], bl);
                    mma_bf16(acc[mt2][nt2], al[mt2], bh);
                }
            }
        }
        __syncthreads();
    }

    // ================= epilogue1: H = relu(C1)*gate -> smem hi/lo ==========
    #pragma unroll
    for (int mt2 = 0; mt2 < 2; mt2++) {
        int rA = m0 + mt2 * 16 + (lane >> 2);
        float gA = s_gate[rA], gB = s_gate[rA + 8];
        #pragma unroll
        for (int nt2 = 0; nt2 < 8; nt2++) {
            int col = n0 + nt2 * 8 + (lane & 3) * 2;
            float c0 = fmaxf(acc[mt2][nt2][0], 0.f) * gA;
            float c1 = fmaxf(acc[mt2][nt2][1], 0.f) * gA;
            float c2 = fmaxf(acc[mt2][nt2][2], 0.f) * gB;
            float c3 = fmaxf(acc[mt2][nt2][3], 0.f) * gB;
            __nv_bfloat16 h0, l0, h1, l1;
            split_bf16(c0, h0, l0); split_bf16(c1, h1, l1);
            *(uint32_t*)(smc + SM_ARENA + H_HI + rA * 272 + col * 2) = pack_bf16(h0, h1);
            *(uint32_t*)(smc + SM_ARENA + H_LO + rA * 272 + col * 2) = pack_bf16(l0, l1);
            split_bf16(c2, h0, l0); split_bf16(c3, h1, l1);
            *(uint32_t*)(smc + SM_ARENA + H_HI + (rA + 8) * 272 + col * 2) = pack_bf16(h0, h1);
            *(uint32_t*)(smc + SM_ARENA + H_LO + (rA + 8) * 272 + col * 2) = pack_bf16(l0, l1);
        }
    }
    __syncthreads();

    // ================= GEMM2: out = H @ values^T, 8 N-chunks ===============
    for (int nch = 0; nch < DDIM / 128; nch++) {
        {   // stage B2: values^T rows d = nch*128 + r, full 128-el rows
            int r = tid >> 1, hf = tid & 1;
            size_t so = ((size_t)e * DDIM + nch * 128 + r) * HDIM + hf * 64;
            #pragma unroll
            for (int j = 0; j < 8; j++) {
                uint32_t off = (uint32_t)r * 272 + hf * 128 + j * 16;
                *(uint4*)(smc + SM_ARENA + B2_HI + off) = ((const uint4*)(g_vth + so))[j];
                *(uint4*)(smc + SM_ARENA + B2_LO + off) = ((const uint4*)(g_vtl + so))[j];
            }
        }
        __syncthreads();

        float a2[2][8][4] = {};
        #pragma unroll
        for (int ks = 0; ks < 8; ks++) {
            const int kloc = ks * 16;
            uint32_t ah[2][4], al[2][4];
            #pragma unroll
            for (int mt2 = 0; mt2 < 2; mt2++) {
                uint32_t ao = (uint32_t)(m0 + mt2 * 16 + rowo) * 272 + (kloc + colx) * 2;
                ldsm_x4(ah[mt2], smb + SM_ARENA + H_HI + ao);
                ldsm_x4(al[mt2], smb + SM_ARENA + H_LO + ao);
            }
            #pragma unroll
            for (int nt2 = 0; nt2 < 8; nt2++) {
                uint32_t bo = (uint32_t)(n0 + nt2 * 8 + brow) * 272 + (kloc + bcol) * 2;
                uint32_t bh[2], bl[2];
                ldsm_x2(bh, smb + SM_ARENA + B2_HI + bo);
                ldsm_x2(bl, smb + SM_ARENA + B2_LO + bo);
                #pragma unroll
                for (int mt2 = 0; mt2 < 2; mt2++) {
                    mma_bf16(a2[mt2][nt2], ah[mt2], bh);
                    mma_bf16(a2[mt2][nt2], ah[mt2], bl);
                    mma_bf16(a2[mt2][nt2], al[mt2], bh);
                }
            }
        }

        // epilogue2: direct stores (4 consecutive lanes cover a 32B sector)
        #pragma unroll
        for (int mt2 = 0; mt2 < 2; mt2++) {
            int rA = m0 + mt2 * 16 + (lane >> 2);
            #pragma unroll
            for (int nt2 = 0; nt2 < 8; nt2++) {
                int col = nch * 128 + n0 + nt2 * 8 + (lane & 3) * 2;
                if (rA < ntok) {
                    float2 v = make_float2(a2[mt2][nt2][0], a2[mt2][nt2][1]);
                    *(float2*)(g_partial + (size_t)s_dest[rA] * DDIM + col) = v;
                }
                if (rA + 8 < ntok) {
                    float2 v = make_float2(a2[mt2][nt2][2], a2[mt2][nt2][3]);
                    *(float2*)(g_partial + (size_t)s_dest[rA + 8] * DDIM + col) = v;
                }
            }
        }
        __syncthreads();
    }
}

// ---------------- kernel 6: gather 4 partial rows per token ----------------
__global__ void gather_kernel(float* __restrict__ out) {
    int i = blockIdx.x * blockDim.x + threadIdx.x;
    int n = i >> 8, c = i & 255;
    const float4* p = (const float4*)g_partial;
    size_t base = (size_t)n * 4 * 256 + c;
    float4 a = p[base], b = p[base + 256], d = p[base + 512], f = p[base + 768];
    float4 r;
    r.x = a.x + b.x + d.x + f.x; r.y = a.y + b.y + d.y + f.y;
    r.z = a.z + b.z + d.z + f.z; r.w = a.w + b.w + d.w + f.w;
    ((float4*)out)[i] = r;
}

// ---------------- launch ----------------------------------------------------
extern "C" void kernel_launch(void* const* d_in, const int* in_sizes, int n_in,
                              void* d_out, int out_size) {
    const float* x      = (const float*)d_in[0];
    const float* W      = (const float*)d_in[1];
    const float* keys   = (const float*)d_in[2];
    const float* values = (const float*)d_in[3];
    float* out = (float*)d_out;

    cudaFuncSetAttribute(moe_ffn_mma, cudaFuncAttributeMaxDynamicSharedMemorySize, SM_TOTAL);

    zero_counts_kernel<<<1, 32>>>();
    gate_topk_kernel<<<NTOK / 4, 128>>>(x, W);
    xcvt_kernel<<<(NTOK * DDIM / 8) / 256, 256>>>(x);
    keysT_kernel<<<dim3(DDIM / 32, HDIM / 32, NEXP), dim3(32, 8)>>>(keys);
    valsT_kernel<<<dim3(HDIM / 32, DDIM / 32, NEXP), dim3(32, 8)>>>(values);
    moe_ffn_mma<<<dim3(CAP / MT, NEXP), 256, SM_TOTAL>>>();
    gather_kernel<<<(NTOK * DDIM / 4) / 256, 256>>>(out);
}

// round 5
// speedup vs baseline: 2.6927x; 1.0501x over previous
#include <cuda_runtime.h>
#include <cuda_bf16.h>
#include <math.h>
#include <stdint.h>

#define NTOK 8192
#define DDIM 1024
#define NEXP 32
#define HDIM 128
#define TOPK 4
#define CAP  8192
#define MT   128          // tokens per FFN tile

// ---------------------------------------------------------------- helpers
__device__ __forceinline__ uint32_t smem_u32(const void* p) {
    uint32_t a;
    asm("{ .reg .u64 t; cvta.to.shared.u64 t, %1; cvt.u32.u64 %0, t; }" : "=r"(a) : "l"(p));
    return a;
}
__device__ __forceinline__ void ldsm_x4(uint32_t* r, uint32_t addr) {
    asm volatile("ldmatrix.sync.aligned.m8n8.x4.shared.b16 {%0,%1,%2,%3}, [%4];"
                 : "=r"(r[0]), "=r"(r[1]), "=r"(r[2]), "=r"(r[3]) : "r"(addr));
}
__device__ __forceinline__ void ldsm_x2(uint32_t* r, uint32_t addr) {
    asm volatile("ldmatrix.sync.aligned.m8n8.x2.shared.b16 {%0,%1}, [%2];"
                 : "=r"(r[0]), "=r"(r[1]) : "r"(addr));
}
__device__ __forceinline__ void mma_bf16(float* c, const uint32_t* a, const uint32_t* b) {
    asm volatile(
        "mma.sync.aligned.m16n8k16.row.col.f32.bf16.bf16.f32 "
        "{%0,%1,%2,%3},{%4,%5,%6,%7},{%8,%9},{%0,%1,%2,%3};"
        : "+f"(c[0]), "+f"(c[1]), "+f"(c[2]), "+f"(c[3])
        : "r"(a[0]), "r"(a[1]), "r"(a[2]), "r"(a[3]), "r"(b[0]), "r"(b[1]));
}
__device__ __forceinline__ void split_bf16(float v, __nv_bfloat16& h, __nv_bfloat16& l) {
    h = __float2bfloat16(v);
    l = __float2bfloat16(v - __bfloat162float(h));
}
__device__ __forceinline__ uint32_t pack_bf16(__nv_bfloat16 a, __nv_bfloat16 b) {
    return (uint32_t)__bfloat16_as_ushort(a) | ((uint32_t)__bfloat16_as_ushort(b) << 16);
}
// cp.async 16B with zero-fill when !valid (src-size 0)
__device__ __forceinline__ void cp16(uint32_t dst, const void* src, bool valid) {
    int sz = valid ? 16 : 0;
    asm volatile("cp.async.cg.shared.global [%0], [%1], 16, %2;"
                 :: "r"(dst), "l"(src), "r"(sz));
}
#define CP_COMMIT() asm volatile("cp.async.commit_group;" ::: "memory")
#define CP_WAIT1()  asm volatile("cp.async.wait_group 1;" ::: "memory")

// ---------------------------------------------------------------- scratch
__device__ int   g_count[NEXP];
__device__ int   g_dest [NEXP * CAP];
__device__ float g_gatew[NEXP * CAP];
__device__ float g_partial[(size_t)NTOK * TOPK * DDIM];
__device__ __nv_bfloat16 g_xhi[(size_t)NTOK * DDIM];
__device__ __nv_bfloat16 g_xlo[(size_t)NTOK * DDIM];
__device__ __nv_bfloat16 g_kth[(size_t)NEXP * HDIM * DDIM];  // keys^T [E][H][D]
__device__ __nv_bfloat16 g_ktl[(size_t)NEXP * HDIM * DDIM];
__device__ __nv_bfloat16 g_vth[(size_t)NEXP * DDIM * HDIM];  // values^T [E][D][H]
__device__ __nv_bfloat16 g_vtl[(size_t)NEXP * DDIM * HDIM];

// ---------------- kernel 0: zero counters ----------------------------------
__global__ void zero_counts_kernel() {
    if (threadIdx.x < NEXP) g_count[threadIdx.x] = 0;
}

// ---------------- kernel 1: gate GEMM + sigmoid + top-4 --------------------
__global__ void gate_topk_kernel(const float* __restrict__ x,
                                 const float* __restrict__ W) {
    __shared__ float sg[4][NEXP];
    const int warp = threadIdx.x >> 5, lane = threadIdx.x & 31;
    const int t = blockIdx.x * 4 + warp;
    float xr[32];
    const float* xp = x + (size_t)t * DDIM;
    #pragma unroll
    for (int j = 0; j < 32; j++) xr[j] = xp[j * 32 + lane];
    for (int e = 0; e < NEXP; e++) {
        const float* w = W + e * DDIM;
        float s = 0.f;
        #pragma unroll
        for (int j = 0; j < 32; j++) s += xr[j] * w[j * 32 + lane];
        #pragma unroll
        for (int o = 16; o > 0; o >>= 1) s += __shfl_xor_sync(0xffffffffu, s, o);
        if (lane == 0) sg[warp][e] = s;
    }
    __syncwarp();
    if (lane == 0) {
        #pragma unroll
        for (int k = 0; k < TOPK; k++) {
            float best = -3.4e38f; int be = 0;
            for (int e = 0; e < NEXP; e++) { float v = sg[warp][e]; if (v > best) { best = v; be = e; } }
            sg[warp][be] = -3.4e38f;
            float gv = 1.0f / (1.0f + expf(-best));
            int pos = atomicAdd(&g_count[be], 1);
            g_dest [be * CAP + pos] = t * TOPK + k;
            g_gatew[be * CAP + pos] = gv;
        }
    }
}

// ---------------- kernel 2: X -> bf16 hi/lo --------------------------------
__global__ void xcvt_kernel(const float* __restrict__ x) {
    size_t i = ((size_t)blockIdx.x * blockDim.x + threadIdx.x) * 8;
    float4 a = *(const float4*)(x + i), b = *(const float4*)(x + i + 4);
    __nv_bfloat16 h[8], l[8];
    split_bf16(a.x, h[0], l[0]); split_bf16(a.y, h[1], l[1]);
    split_bf16(a.z, h[2], l[2]); split_bf16(a.w, h[3], l[3]);
    split_bf16(b.x, h[4], l[4]); split_bf16(b.y, h[5], l[5]);
    split_bf16(b.z, h[6], l[6]); split_bf16(b.w, h[7], l[7]);
    *(uint4*)(g_xhi + i) = *(uint4*)h;
    *(uint4*)(g_xlo + i) = *(uint4*)l;
}

// ---------------- kernel 3: keys [E][D][H] -> keys^T [E][H][D] hi/lo -------
__global__ void keysT_kernel(const float* __restrict__ keys) {
    __shared__ float tile[32][33];
    int e = blockIdx.z, d0 = blockIdx.x * 32, h0 = blockIdx.y * 32;
    int tx = threadIdx.x, ty = threadIdx.y;
    const float* src = keys + (size_t)e * DDIM * HDIM;
    #pragma unroll
    for (int i = 0; i < 4; i++)
        tile[ty + i * 8][tx] = src[(size_t)(d0 + ty + i * 8) * HDIM + h0 + tx];
    __syncthreads();
    #pragma unroll
    for (int i = 0; i < 4; i++) {
        float v = tile[tx][ty + i * 8];
        __nv_bfloat16 h, l; split_bf16(v, h, l);
        size_t o = ((size_t)e * HDIM + h0 + ty + i * 8) * DDIM + d0 + tx;
        g_kth[o] = h; g_ktl[o] = l;
    }
}

// ---------------- kernel 4: values [E][H][D] -> values^T [E][D][H] hi/lo ---
__global__ void valsT_kernel(const float* __restrict__ values) {
    __shared__ float tile[32][33];
    int e = blockIdx.z, h0 = blockIdx.x * 32, d0 = blockIdx.y * 32;
    int tx = threadIdx.x, ty = threadIdx.y;
    const float* src = values + (size_t)e * HDIM * DDIM;
    #pragma unroll
    for (int i = 0; i < 4; i++)
        tile[ty + i * 8][tx] = src[(size_t)(h0 + ty + i * 8) * DDIM + d0 + tx];
    __syncthreads();
    #pragma unroll
    for (int i = 0; i < 4; i++) {
        float v = tile[tx][ty + i * 8];
        __nv_bfloat16 h, l; split_bf16(v, h, l);
        size_t o = ((size_t)e * DDIM + d0 + ty + i * 8) * HDIM + h0 + tx;
        g_vth[o] = h; g_vtl[o] = l;
    }
}

// ---------------- kernel 5: grouped FFN via mma.sync bf16 + cp.async -------
// smem arena (dynamic, 1024-aligned base):
//   GEMM1 (stage s at s*73728): A1hi +0 | A1lo +18432 | B1hi +36864 | B1lo +55296
//        rows stride 144, 64-el K-chunks
//   GEMM2: Hhi @0 | Hlo @34816 | B2 stage s @ 69632 + s*69632 (hi +0, lo +34816)
//        rows stride 272, 128-el rows
#define SM_DEST  0
#define SM_GATE  512
#define SM_ARENA 1024
#define G1_STAGE 73728
#define H_HI  0
#define H_LO  34816
#define B2_BASE 69632
#define B2_STAGE 69632
#define SM_TOTAL (1024 + 208896)

__global__ __launch_bounds__(256, 1) void moe_ffn_mma() {
    extern __shared__ char smc[];
    const uint32_t smb = smem_u32(smc);
    const int e = blockIdx.y;
    const int cnt = g_count[e];
    const int start = blockIdx.x * MT;
    if (start >= cnt) return;
    const int ntok = min(MT, cnt - start);

    const int tid = threadIdx.x, lane = tid & 31, wid = tid >> 5;
    const int m0 = (wid & 3) * 32;     // warp M offset (4 warps x 32)
    const int n0 = (wid >> 2) * 64;    // warp N offset (2 warps x 64)

    int*   s_dest = (int*)(smc + SM_DEST);
    float* s_gate = (float*)(smc + SM_GATE);
    if (tid < MT) {
        if (tid < ntok) {
            int idx = e * CAP + start + tid;
            s_dest[tid] = g_dest[idx];
            s_gate[tid] = g_gatew[idx];
        } else { s_dest[tid] = 0; s_gate[tid] = 0.f; }
    }
    __syncthreads();

    // staging lane geometry (all staging: 2 threads per row)
    const int srow = tid >> 1, shf = tid & 1;
    const bool svalid = srow < ntok;
    const size_t arowA = (size_t)(s_dest[srow] >> 2) * DDIM;       // gathered token row
    const size_t browK = ((size_t)e * HDIM + srow) * DDIM;         // keys^T row

    // ldmatrix lane address components
    const int rowo = (lane & 7) + ((lane >> 3) & 1) * 8;
    const int colx = (lane >> 4) * 8;
    const int brow = lane & 7;
    const int bcol = ((lane >> 3) & 1) * 8;

    // ---- GEMM1 stage loader ----
    auto stage1 = [&](int s, int kc) {
        uint32_t base = smb + SM_ARENA + s * G1_STAGE + (uint32_t)srow * 144 + shf * 64;
        size_t ko = kc * 64 + shf * 32;
        const __nv_bfloat16* pa_h = g_xhi + arowA + ko;
        const __nv_bfloat16* pa_l = g_xlo + arowA + ko;
        const __nv_bfloat16* pb_h = g_kth + browK + ko;
        const __nv_bfloat16* pb_l = g_ktl + browK + ko;
        #pragma unroll
        for (int j = 0; j < 4; j++) {
            cp16(base +         j * 16, pa_h + j * 8, svalid);
            cp16(base + 18432 + j * 16, pa_l + j * 8, svalid);
            cp16(base + 36864 + j * 16, pb_h + j * 8, true);
            cp16(base + 55296 + j * 16, pb_l + j * 8, true);
        }
    };
    // ---- GEMM2 stage loader ----
    auto stage2 = [&](int s, int nch) {
        size_t so = ((size_t)e * DDIM + nch * 128 + srow) * HDIM + shf * 64;
        uint32_t base = smb + SM_ARENA + B2_BASE + s * B2_STAGE
                      + (uint32_t)srow * 272 + shf * 128;
        #pragma unroll
        for (int j = 0; j < 8; j++) {
            cp16(base +         j * 16, g_vth + so + j * 8, true);
            cp16(base + 34816 + j * 16, g_vtl + so + j * 8, true);
        }
    };

    float acc[2][8][4] = {};

    // ================= GEMM1: C1 = X @ keys^T (3-pass split) ===============
    stage1(0, 0);
    CP_COMMIT();
    for (int kc = 0; kc < DDIM / 64; kc++) {
        if (kc + 1 < DDIM / 64) stage1((kc + 1) & 1, kc + 1);
        CP_COMMIT();
        CP_WAIT1();
        __syncthreads();

        const uint32_t sb = smb + SM_ARENA + (kc & 1) * G1_STAGE;
        #pragma unroll
        for (int ks = 0; ks < 4; ks++) {
            const int kloc = ks * 16;
            uint32_t ah[2][4], al[2][4];
            #pragma unroll
            for (int mt2 = 0; mt2 < 2; mt2++) {
                uint32_t ao = (uint32_t)(m0 + mt2 * 16 + rowo) * 144 + (kloc + colx) * 2;
                ldsm_x4(ah[mt2], sb + ao);
                ldsm_x4(al[mt2], sb + 18432 + ao);
            }
            #pragma unroll
            for (int nt2 = 0; nt2 < 8; nt2++) {
                uint32_t bo = (uint32_t)(n0 + nt2 * 8 + brow) * 144 + (kloc + bcol) * 2;
                uint32_t bh[2], bl[2];
                ldsm_x2(bh, sb + 36864 + bo);
                ldsm_x2(bl, sb + 55296 + bo);
                #pragma unroll
                for (int mt2 = 0; mt2 < 2; mt2++) {
                    mma_bf16(acc[mt2][nt2], ah[mt2], bh);
                    mma_bf16(acc[mt2][nt2], ah[mt2], bl);
                    mma_bf16(acc[mt2][nt2], al[mt2], bh);
                }
            }
        }
        __syncthreads();
    }

    // prefetch first B2 tile (overlaps epilogue1 register math)
    stage2(0, 0);
    CP_COMMIT();

    // ================= epilogue1: H = relu(C1)*gate -> smem hi/lo ==========
    #pragma unroll
    for (int mt2 = 0; mt2 < 2; mt2++) {
        int rA = m0 + mt2 * 16 + (lane >> 2);
        float gA = s_gate[rA], gB = s_gate[rA + 8];
        #pragma unroll
        for (int nt2 = 0; nt2 < 8; nt2++) {
            int col = n0 + nt2 * 8 + (lane & 3) * 2;
            float c0 = fmaxf(acc[mt2][nt2][0], 0.f) * gA;
            float c1 = fmaxf(acc[mt2][nt2][1], 0.f) * gA;
            float c2 = fmaxf(acc[mt2][nt2][2], 0.f) * gB;
            float c3 = fmaxf(acc[mt2][nt2][3], 0.f) * gB;
            __nv_bfloat16 h0, l0, h1, l1;
            split_bf16(c0, h0, l0); split_bf16(c1, h1, l1);
            *(uint32_t*)(smc + SM_ARENA + H_HI + rA * 272 + col * 2) = pack_bf16(h0, h1);
            *(uint32_t*)(smc + SM_ARENA + H_LO + rA * 272 + col * 2) = pack_bf16(l0, l1);
            split_bf16(c2, h0, l0); split_bf16(c3, h1, l1);
            *(uint32_t*)(smc + SM_ARENA + H_HI + (rA + 8) * 272 + col * 2) = pack_bf16(h0, h1);
            *(uint32_t*)(smc + SM_ARENA + H_LO + (rA + 8) * 272 + col * 2) = pack_bf16(l0, l1);
        }
    }

    // ================= GEMM2: out = H @ values^T, 8 N-chunks ===============
    for (int nch = 0; nch < DDIM / 128; nch++) {
        if (nch + 1 < DDIM / 128) stage2((nch + 1) & 1, nch + 1);
        CP_COMMIT();
        CP_WAIT1();
        __syncthreads();

        const uint32_t hb = smb + SM_ARENA;
        const uint32_t b2 = smb + SM_ARENA + B2_BASE + (nch & 1) * B2_STAGE;
        float a2[2][8][4] = {};
        #pragma unroll
        for (int ks = 0; ks < 8; ks++) {
            const int kloc = ks * 16;
            uint32_t ah[2][4], al[2][4];
            #pragma unroll
            for (int mt2 = 0; mt2 < 2; mt2++) {
                uint32_t ao = (uint32_t)(m0 + mt2 * 16 + rowo) * 272 + (kloc + colx) * 2;
                ldsm_x4(ah[mt2], hb + H_HI + ao);
                ldsm_x4(al[mt2], hb + H_LO + ao);
            }
            #pragma unroll
            for (int nt2 = 0; nt2 < 8; nt2++) {
                uint32_t bo = (uint32_t)(n0 + nt2 * 8 + brow) * 272 + (kloc + bcol) * 2;
                uint32_t bh[2], bl[2];
                ldsm_x2(bh, b2 + bo);
                ldsm_x2(bl, b2 + 34816 + bo);
                #pragma unroll
                for (int mt2 = 0; mt2 < 2; mt2++) {
                    mma_bf16(a2[mt2][nt2], ah[mt2], bh);
                    mma_bf16(a2[mt2][nt2], ah[mt2], bl);
                    mma_bf16(a2[mt2][nt2], al[mt2], bh);
                }
            }
        }

        // epilogue2: direct stores (4 consecutive lanes cover a 32B sector)
        #pragma unroll
        for (int mt2 = 0; mt2 < 2; mt2++) {
            int rA = m0 + mt2 * 16 + (lane >> 2);
            #pragma unroll
            for (int nt2 = 0; nt2 < 8; nt2++) {
                int col = nch * 128 + n0 + nt2 * 8 + (lane & 3) * 2;
                if (rA < ntok) {
                    float2 v = make_float2(a2[mt2][nt2][0], a2[mt2][nt2][1]);
                    *(float2*)(g_partial + (size_t)s_dest[rA] * DDIM + col) = v;
                }
                if (rA + 8 < ntok) {
                    float2 v = make_float2(a2[mt2][nt2][2], a2[mt2][nt2][3]);
                    *(float2*)(g_partial + (size_t)s_dest[rA + 8] * DDIM + col) = v;
                }
            }
        }
        __syncthreads();
    }
}

// ---------------- kernel 6: gather 4 partial rows per token ----------------
__global__ void gather_kernel(float* __restrict__ out) {
    int i = blockIdx.x * blockDim.x + threadIdx.x;
    int n = i >> 8, c = i & 255;
    const float4* p = (const float4*)g_partial;
    size_t base = (size_t)n * 4 * 256 + c;
    float4 a = p[base], b = p[base + 256], d = p[base + 512], f = p[base + 768];
    float4 r;
    r.x = a.x + b.x + d.x + f.x; r.y = a.y + b.y + d.y + f.y;
    r.z = a.z + b.z + d.z + f.z; r.w = a.w + b.w + d.w + f.w;
    ((float4*)out)[i] = r;
}

// ---------------- launch ----------------------------------------------------
extern "C" void kernel_launch(void* const* d_in, const int* in_sizes, int n_in,
                              void* d_out, int out_size) {
    const float* x      = (const float*)d_in[0];
    const float* W      = (const float*)d_in[1];
    const float* keys   = (const float*)d_in[2];
    const float* values = (const float*)d_in[3];
    float* out = (float*)d_out;

    cudaFuncSetAttribute(moe_ffn_mma, cudaFuncAttributeMaxDynamicSharedMemorySize, SM_TOTAL);

    zero_counts_kernel<<<1, 32>>>();
    gate_topk_kernel<<<NTOK / 4, 128>>>(x, W);
    xcvt_kernel<<<(NTOK * DDIM / 8) / 256, 256>>>(x);
    keysT_kernel<<<dim3(DDIM / 32, HDIM / 32, NEXP), dim3(32, 8)>>>(keys);
    valsT_kernel<<<dim3(HDIM / 32, DDIM / 32, NEXP), dim3(32, 8)>>>(values);
    moe_ffn_mma<<<dim3(CAP / MT, NEXP), 256, SM_TOTAL>>>();
    gather_kernel<<<(NTOK * DDIM / 4) / 256, 256>>>(out);
}

// round 6
// speedup vs baseline: 3.1968x; 1.1872x over previous
#include <cuda_runtime.h>
#include <cuda_fp16.h>
#include <math.h>
#include <stdint.h>

#define NTOK 8192
#define DDIM 1024
#define NEXP 32
#define HDIM 128
#define TOPK 4
#define CAP  8192
#define MT   128          // tokens per FFN tile

// ---------------------------------------------------------------- helpers
__device__ __forceinline__ uint32_t smem_u32(const void* p) {
    uint32_t a;
    asm("{ .reg .u64 t; cvta.to.shared.u64 t, %1; cvt.u32.u64 %0, t; }" : "=r"(a) : "l"(p));
    return a;
}
__device__ __forceinline__ void ldsm_x4(uint32_t* r, uint32_t addr) {
    asm volatile("ldmatrix.sync.aligned.m8n8.x4.shared.b16 {%0,%1,%2,%3}, [%4];"
                 : "=r"(r[0]), "=r"(r[1]), "=r"(r[2]), "=r"(r[3]) : "r"(addr));
}
__device__ __forceinline__ void mma_f16(float* c, const uint32_t* a, const uint32_t* b) {
    asm volatile(
        "mma.sync.aligned.m16n8k16.row.col.f32.f16.f16.f32 "
        "{%0,%1,%2,%3},{%4,%5,%6,%7},{%8,%9},{%0,%1,%2,%3};"
        : "+f"(c[0]), "+f"(c[1]), "+f"(c[2]), "+f"(c[3])
        : "r"(a[0]), "r"(a[1]), "r"(a[2]), "r"(a[3]), "r"(b[0]), "r"(b[1]));
}
__device__ __forceinline__ void split_f16(float v, __half& h, __half& l) {
    h = __float2half(v);
    l = __float2half(v - __half2float(h));
}
__device__ __forceinline__ uint32_t pack_f16(__half a, __half b) {
    return (uint32_t)__half_as_ushort(a) | ((uint32_t)__half_as_ushort(b) << 16);
}
__device__ __forceinline__ void cp16(uint32_t dst, const void* src, bool valid) {
    int sz = valid ? 16 : 0;
    asm volatile("cp.async.cg.shared.global [%0], [%1], 16, %2;"
                 :: "r"(dst), "l"(src), "r"(sz));
}
#define CP_COMMIT() asm volatile("cp.async.commit_group;" ::: "memory")
#define CP_WAIT1()  asm volatile("cp.async.wait_group 1;" ::: "memory")

// ---------------------------------------------------------------- scratch
__device__ int   g_count[NEXP];
__device__ int   g_dest [NEXP * CAP];
__device__ float g_gatew[NEXP * CAP];
__device__ float g_partial[(size_t)NTOK * TOPK * DDIM];
__device__ __half g_xhi[(size_t)NTOK * DDIM];
__device__ __half g_xlo[(size_t)NTOK * DDIM];
__device__ __half g_kth[(size_t)NEXP * HDIM * DDIM];  // keys^T  [E][H][D] fp16
__device__ __half g_vth[(size_t)NEXP * DDIM * HDIM];  // values^T [E][D][H] fp16

// ---------------- kernel 0: zero expert counters ---------------------------
__global__ void zero_counts_kernel() {
    if (threadIdx.x < NEXP) g_count[threadIdx.x] = 0;
}

// ---------------- kernel 1: gate GEMM + sigmoid + top-4 --------------------
__global__ void gate_topk_kernel(const float* __restrict__ x,
                                 const float* __restrict__ W) {
    __shared__ float sg[4][NEXP];
    const int warp = threadIdx.x >> 5, lane = threadIdx.x & 31;
    const int t = blockIdx.x * 4 + warp;
    float xr[32];
    const float* xp = x + (size_t)t * DDIM;
    #pragma unroll
    for (int j = 0; j < 32; j++) xr[j] = xp[j * 32 + lane];
    for (int e = 0; e < NEXP; e++) {
        const float* w = W + e * DDIM;
        float s = 0.f;
        #pragma unroll
        for (int j = 0; j < 32; j++) s += xr[j] * w[j * 32 + lane];
        #pragma unroll
        for (int o = 16; o > 0; o >>= 1) s += __shfl_xor_sync(0xffffffffu, s, o);
        if (lane == 0) sg[warp][e] = s;
    }
    __syncwarp();
    if (lane == 0) {
        #pragma unroll
        for (int k = 0; k < TOPK; k++) {
            float best = -3.4e38f; int be = 0;
            for (int e = 0; e < NEXP; e++) { float v = sg[warp][e]; if (v > best) { best = v; be = e; } }
            sg[warp][be] = -3.4e38f;
            float gv = 1.0f / (1.0f + expf(-best));
            int pos = atomicAdd(&g_count[be], 1);
            g_dest [be * CAP + pos] = t * TOPK + k;
            g_gatew[be * CAP + pos] = gv;
        }
    }
}

// ---------------- kernel 2 (merged): all fp16 conversions ------------------
// grid (4096, 3): y=0 X->hi/lo, y=1 keys^T (hi), y=2 values^T (hi)
__global__ void convert_kernel(const float* __restrict__ x,
                               const float* __restrict__ keys,
                               const float* __restrict__ values) {
    const int tid = threadIdx.x;
    if (blockIdx.y == 0) {
        size_t i = ((size_t)blockIdx.x * 256 + tid) * 8;
        float4 a = *(const float4*)(x + i), b = *(const float4*)(x + i + 4);
        __half h[8], l[8];
        split_f16(a.x, h[0], l[0]); split_f16(a.y, h[1], l[1]);
        split_f16(a.z, h[2], l[2]); split_f16(a.w, h[3], l[3]);
        split_f16(b.x, h[4], l[4]); split_f16(b.y, h[5], l[5]);
        split_f16(b.z, h[6], l[6]); split_f16(b.w, h[7], l[7]);
        *(uint4*)(g_xhi + i) = *(uint4*)h;
        *(uint4*)(g_xlo + i) = *(uint4*)l;
    } else if (blockIdx.y == 1) {
        __shared__ float tile[32][33];
        int bx = blockIdx.x, e = bx >> 7, rem = bx & 127;
        int d0 = (rem & 31) * 32, h0 = (rem >> 5) * 32;
        int tx = tid & 31, ty = tid >> 5;
        const float* src = keys + (size_t)e * DDIM * HDIM;
        #pragma unroll
        for (int i = 0; i < 4; i++)
            tile[ty + i * 8][tx] = src[(size_t)(d0 + ty + i * 8) * HDIM + h0 + tx];
        __syncthreads();
        #pragma unroll
        for (int i = 0; i < 4; i++)
            g_kth[((size_t)e * HDIM + h0 + ty + i * 8) * DDIM + d0 + tx] =
                __float2half(tile[tx][ty + i * 8]);
    } else {
        __shared__ float tile[32][33];
        int bx = blockIdx.x, e = bx >> 7, rem = bx & 127;
        int h0 = (rem & 3) * 32, d0 = (rem >> 2) * 32;
        int tx = tid & 31, ty = tid >> 5;
        const float* src = values + (size_t)e * HDIM * DDIM;
        #pragma unroll
        for (int i = 0; i < 4; i++)
            tile[ty + i * 8][tx] = src[(size_t)(h0 + ty + i * 8) * DDIM + d0 + tx];
        __syncthreads();
        #pragma unroll
        for (int i = 0; i < 4; i++)
            g_vth[((size_t)e * DDIM + d0 + ty + i * 8) * HDIM + h0 + tx] =
                __float2half(tile[tx][ty + i * 8]);
    }
}

// ---------------- kernel 3: grouped FFN, fp16 2-pass split -----------------
// smem (dynamic, per CTA 111616 B -> 2 CTA/SM):
//   0 s_dest[128] | 512 s_gate[128]
//   SM_ARENA = 1024:
//     GEMM1 stage s @ s*55296: Ahi +0 | Alo +18432 | Bhi +36864 (rows 144B)
//     GEMM2: Hhi @+0 (34816) | Hlo @+34816 | B2 stage s @ +69632 + s*17408 (rows 272B)
#define SM_DEST  0
#define SM_GATE  512
#define SM_ARENA 1024
#define G1_STAGE 55296
#define G1_ALO   18432
#define G1_BHI   36864
#define H_LO_OFF 34816
#define B2_OFF   69632
#define B2_STAGE 17408
#define SM_TOTAL (1024 + 110592)

__global__ __launch_bounds__(256, 2) void moe_ffn_mma() {
    extern __shared__ char smc[];
    const uint32_t smb = smem_u32(smc);
    const int e = blockIdx.y;
    const int cnt = g_count[e];
    const int start = blockIdx.x * MT;
    if (start >= cnt) return;
    const int ntok = min(MT, cnt - start);

    const int tid = threadIdx.x, lane = tid & 31, wid = tid >> 5;
    const int m0 = (wid & 3) * 32;        // 4 warps in M
    const int n0 = (wid >> 2) * 64;       // 2 warps in N (GEMM1: 64 cols)
    const int n02 = (wid >> 2) * 32;      // GEMM2: 32 cols of 64-col chunk

    int*   s_dest = (int*)(smc + SM_DEST);
    float* s_gate = (float*)(smc + SM_GATE);
    if (tid < MT) {
        if (tid < ntok) {
            int idx = e * CAP + start + tid;
            s_dest[tid] = g_dest[idx];
            s_gate[tid] = g_gatew[idx];
        } else { s_dest[tid] = 0; s_gate[tid] = 0.f; }
    }
    __syncthreads();

    // staging geometry
    const int srow = tid >> 1, shf = tid & 1;           // GEMM1: 2 thr/row
    const bool svalid = srow < ntok;
    const size_t arowA = (size_t)(s_dest[srow] >> 2) * DDIM;
    const size_t browK = ((size_t)e * HDIM + srow) * DDIM;
    const int srow2 = tid >> 2, shf2 = tid & 3;         // GEMM2: 4 thr/row

    // ldmatrix lane address components (shared by A and B x4 loads)
    const int rowo = (lane & 7) + ((lane >> 3) & 1) * 8;
    const int colx = (lane >> 4) * 8;

    auto stage1 = [&](int s, int kc) {
        uint32_t base = smb + SM_ARENA + s * G1_STAGE + (uint32_t)srow * 144 + shf * 64;
        size_t ko = (size_t)kc * 64 + shf * 32;
        #pragma unroll
        for (int j = 0; j < 4; j++) {
            cp16(base +          j * 16, g_xhi + arowA + ko + j * 8, svalid);
            cp16(base + G1_ALO + j * 16, g_xlo + arowA + ko + j * 8, svalid);
            cp16(base + G1_BHI + j * 16, g_kth + browK + ko + j * 8, true);
        }
    };
    auto stage2 = [&](int s, int nch) {
        size_t so = ((size_t)e * DDIM + nch * 64 + srow2) * HDIM + shf2 * 32;
        uint32_t base = smb + SM_ARENA + B2_OFF + s * B2_STAGE
                      + (uint32_t)srow2 * 272 + shf2 * 64;
        #pragma unroll
        for (int j = 0; j < 4; j++)
            cp16(base + j * 16, g_vth + so + j * 8, true);
    };

    float acc[2][8][4] = {};

    // ================= GEMM1: C1 = X @ keys^T (2-pass: Xhi,Xlo vs Khi) =====
    stage1(0, 0);
    CP_COMMIT();
    for (int kc = 0; kc < DDIM / 64; kc++) {
        if (kc + 1 < DDIM / 64) stage1((kc + 1) & 1, kc + 1);
        CP_COMMIT();
        CP_WAIT1();
        __syncthreads();

        const uint32_t sb = smb + SM_ARENA + (kc & 1) * G1_STAGE;
        #pragma unroll
        for (int ks = 0; ks < 4; ks++) {
            const int kloc = ks * 16;
            uint32_t ah[2][4], al[2][4], b[8][2];
            #pragma unroll
            for (int mt2 = 0; mt2 < 2; mt2++) {
                uint32_t ao = (uint32_t)(m0 + mt2 * 16 + rowo) * 144 + (kloc + colx) * 2;
                ldsm_x4(ah[mt2], sb + ao);
                ldsm_x4(al[mt2], sb + G1_ALO + ao);
            }
            #pragma unroll
            for (int p = 0; p < 4; p++) {   // each x4 covers 2 n-octets
                uint32_t bo = (uint32_t)(n0 + p * 16 + rowo) * 144 + (kloc + colx) * 2;
                uint32_t bq[4];
                ldsm_x4(bq, sb + G1_BHI + bo);
                b[2 * p][0] = bq[0]; b[2 * p][1] = bq[2];
                b[2 * p + 1][0] = bq[1]; b[2 * p + 1][1] = bq[3];
            }
            #pragma unroll
            for (int nt2 = 0; nt2 < 8; nt2++)
                #pragma unroll
                for (int mt2 = 0; mt2 < 2; mt2++) {
                    mma_f16(acc[mt2][nt2], ah[mt2], b[nt2]);
                    mma_f16(acc[mt2][nt2], al[mt2], b[nt2]);
                }
        }
        __syncthreads();
    }

    // prefetch first B2 tile (overlaps epilogue1 register math)
    stage2(0, 0);
    CP_COMMIT();

    // ================= epilogue1: H = relu(C1)*gate -> smem fp16 hi/lo =====
    #pragma unroll
    for (int mt2 = 0; mt2 < 2; mt2++) {
        int rA = m0 + mt2 * 16 + (lane >> 2);
        float gA = s_gate[rA], gB = s_gate[rA + 8];
        #pragma unroll
        for (int nt2 = 0; nt2 < 8; nt2++) {
            int col = n0 + nt2 * 8 + (lane & 3) * 2;
            float c0 = fmaxf(acc[mt2][nt2][0], 0.f) * gA;
            float c1 = fmaxf(acc[mt2][nt2][1], 0.f) * gA;
            float c2 = fmaxf(acc[mt2][nt2][2], 0.f) * gB;
            float c3 = fmaxf(acc[mt2][nt2][3], 0.f) * gB;
            __half h0, l0, h1, l1;
            split_f16(c0, h0, l0); split_f16(c1, h1, l1);
            *(uint32_t*)(smc + SM_ARENA + rA * 272 + col * 2) = pack_f16(h0, h1);
            *(uint32_t*)(smc + SM_ARENA + H_LO_OFF + rA * 272 + col * 2) = pack_f16(l0, l1);
            split_f16(c2, h0, l0); split_f16(c3, h1, l1);
            *(uint32_t*)(smc + SM_ARENA + (rA + 8) * 272 + col * 2) = pack_f16(h0, h1);
            *(uint32_t*)(smc + SM_ARENA + H_LO_OFF + (rA + 8) * 272 + col * 2) = pack_f16(l0, l1);
        }
    }

    // ================= GEMM2: out = H @ values^T, 16 chunks of 64 cols =====
    for (int nch = 0; nch < DDIM / 64; nch++) {
        if (nch + 1 < DDIM / 64) stage2((nch + 1) & 1, nch + 1);
        CP_COMMIT();
        CP_WAIT1();
        __syncthreads();

        const uint32_t hb = smb + SM_ARENA;
        const uint32_t b2 = smb + SM_ARENA + B2_OFF + (nch & 1) * B2_STAGE;
        float a2[2][4][4] = {};
        #pragma unroll
        for (int ks = 0; ks < 8; ks++) {
            const int kloc = ks * 16;
            uint32_t ah[2][4], al[2][4], b[4][2];
            #pragma unroll
            for (int mt2 = 0; mt2 < 2; mt2++) {
                uint32_t ao = (uint32_t)(m0 + mt2 * 16 + rowo) * 272 + (kloc + colx) * 2;
                ldsm_x4(ah[mt2], hb + ao);
                ldsm_x4(al[mt2], hb + H_LO_OFF + ao);
            }
            #pragma unroll
            for (int p = 0; p < 2; p++) {
                uint32_t bo = (uint32_t)(n02 + p * 16 + rowo) * 272 + (kloc + colx) * 2;
                uint32_t bq[4];
                ldsm_x4(bq, b2 + bo);
                b[2 * p][0] = bq[0]; b[2 * p][1] = bq[2];
                b[2 * p + 1][0] = bq[1]; b[2 * p + 1][1] = bq[3];
            }
            #pragma unroll
            for (int nt2 = 0; nt2 < 4; nt2++)
                #pragma unroll
                for (int mt2 = 0; mt2 < 2; mt2++) {
                    mma_f16(a2[mt2][nt2], ah[mt2], b[nt2]);
                    mma_f16(a2[mt2][nt2], al[mt2], b[nt2]);
                }
        }

        // epilogue2: direct stores (4 consecutive lanes = one 32B sector)
        #pragma unroll
        for (int mt2 = 0; mt2 < 2; mt2++) {
            int rA = m0 + mt2 * 16 + (lane >> 2);
            #pragma unroll
            for (int nt2 = 0; nt2 < 4; nt2++) {
                int col = nch * 64 + n02 + nt2 * 8 + (lane & 3) * 2;
                if (rA < ntok) {
                    float2 v = make_float2(a2[mt2][nt2][0], a2[mt2][nt2][1]);
                    *(float2*)(g_partial + (size_t)s_dest[rA] * DDIM + col) = v;
                }
                if (rA + 8 < ntok) {
                    float2 v = make_float2(a2[mt2][nt2][2], a2[mt2][nt2][3]);
                    *(float2*)(g_partial + (size_t)s_dest[rA + 8] * DDIM + col) = v;
                }
            }
        }
        __syncthreads();
    }
}

// ---------------- kernel 4: gather 4 partial rows per token ----------------
__global__ void gather_kernel(float* __restrict__ out) {
    int i = blockIdx.x * blockDim.x + threadIdx.x;
    int n = i >> 8, c = i & 255;
    const float4* p = (const float4*)g_partial;
    size_t base = (size_t)n * 4 * 256 + c;
    float4 a = p[base], b = p[base + 256], d = p[base + 512], f = p[base + 768];
    float4 r;
    r.x = a.x + b.x + d.x + f.x; r.y = a.y + b.y + d.y + f.y;
    r.z = a.z + b.z + d.z + f.z; r.w = a.w + b.w + d.w + f.w;
    ((float4*)out)[i] = r;
}

// ---------------- launch ----------------------------------------------------
extern "C" void kernel_launch(void* const* d_in, const int* in_sizes, int n_in,
                              void* d_out, int out_size) {
    const float* x      = (const float*)d_in[0];
    const float* W      = (const float*)d_in[1];
    const float* keys   = (const float*)d_in[2];
    const float* values = (const float*)d_in[3];
    float* out = (float*)d_out;

    cudaFuncSetAttribute(moe_ffn_mma, cudaFuncAttributeMaxDynamicSharedMemorySize, SM_TOTAL);

    zero_counts_kernel<<<1, 32>>>();
    gate_topk_kernel<<<NTOK / 4, 128>>>(x, W);
    convert_kernel<<<dim3(4096, 3), 256>>>(x, keys, values);
    moe_ffn_mma<<<dim3(CAP / MT, NEXP), 256, SM_TOTAL>>>();
    gather_kernel<<<(NTOK * DDIM / 4) / 256, 256>>>(out);
}

// round 7
// speedup vs baseline: 3.9103x; 1.2232x over previous
#include <cuda_runtime.h>
#include <cuda_fp16.h>
#include <math.h>
#include <stdint.h>

#define NTOK 8192
#define DDIM 1024
#define NEXP 32
#define HDIM 128
#define TOPK 4
#define CAP  8192
#define MT   128          // tokens per FFN tile

// ---------------------------------------------------------------- helpers
__device__ __forceinline__ uint32_t smem_u32(const void* p) {
    uint32_t a;
    asm("{ .reg .u64 t; cvta.to.shared.u64 t, %1; cvt.u32.u64 %0, t; }" : "=r"(a) : "l"(p));
    return a;
}
__device__ __forceinline__ void ldsm_x4(uint32_t* r, uint32_t addr) {
    asm volatile("ldmatrix.sync.aligned.m8n8.x4.shared.b16 {%0,%1,%2,%3}, [%4];"
                 : "=r"(r[0]), "=r"(r[1]), "=r"(r[2]), "=r"(r[3]) : "r"(addr));
}
__device__ __forceinline__ void mma_f16(float* c, const uint32_t* a, const uint32_t* b) {
    asm volatile(
        "mma.sync.aligned.m16n8k16.row.col.f32.f16.f16.f32 "
        "{%0,%1,%2,%3},{%4,%5,%6,%7},{%8,%9},{%0,%1,%2,%3};"
        : "+f"(c[0]), "+f"(c[1]), "+f"(c[2]), "+f"(c[3])
        : "r"(a[0]), "r"(a[1]), "r"(a[2]), "r"(a[3]), "r"(b[0]), "r"(b[1]));
}
__device__ __forceinline__ uint32_t pack_f16(float a, float b) {
    __half2 h = __floats2half2_rn(a, b);
    return *(uint32_t*)&h;
}
__device__ __forceinline__ void cp16(uint32_t dst, const void* src, bool valid) {
    int sz = valid ? 16 : 0;
    asm volatile("cp.async.cg.shared.global [%0], [%1], 16, %2;"
                 :: "r"(dst), "l"(src), "r"(sz));
}
#define CP_COMMIT() asm volatile("cp.async.commit_group;" ::: "memory")
#define CP_WAIT1()  asm volatile("cp.async.wait_group 1;" ::: "memory")

// ---------------------------------------------------------------- scratch
__device__ int   g_count[NEXP];
__device__ int   g_dest [NEXP * CAP];
__device__ float g_gatew[NEXP * CAP];
__device__ float g_partial[(size_t)NTOK * TOPK * DDIM];
__device__ __half g_xh [(size_t)NTOK * DDIM];                 // X fp16
__device__ __half g_kth[(size_t)NEXP * HDIM * DDIM];          // keys^T  [E][H][D]
__device__ __half g_vth[(size_t)NEXP * DDIM * HDIM];          // values^T [E][D][H]

// ---------------- kernel 0: zero expert counters ---------------------------
__global__ void zero_counts_kernel() {
    if (threadIdx.x < NEXP) g_count[threadIdx.x] = 0;
}

// ---------------- kernel 1: gate GEMM + sigmoid + top-4 --------------------
__global__ void gate_topk_kernel(const float* __restrict__ x,
                                 const float* __restrict__ W) {
    __shared__ float sg[4][NEXP];
    const int warp = threadIdx.x >> 5, lane = threadIdx.x & 31;
    const int t = blockIdx.x * 4 + warp;
    float xr[32];
    const float* xp = x + (size_t)t * DDIM;
    #pragma unroll
    for (int j = 0; j < 32; j++) xr[j] = xp[j * 32 + lane];
    for (int e = 0; e < NEXP; e++) {
        const float* w = W + e * DDIM;
        float s = 0.f;
        #pragma unroll
        for (int j = 0; j < 32; j++) s += xr[j] * w[j * 32 + lane];
        #pragma unroll
        for (int o = 16; o > 0; o >>= 1) s += __shfl_xor_sync(0xffffffffu, s, o);
        if (lane == 0) sg[warp][e] = s;
    }
    __syncwarp();
    if (lane == 0) {
        #pragma unroll
        for (int k = 0; k < TOPK; k++) {
            float best = -3.4e38f; int be = 0;
            for (int e = 0; e < NEXP; e++) { float v = sg[warp][e]; if (v > best) { best = v; be = e; } }
            sg[warp][be] = -3.4e38f;
            float gv = 1.0f / (1.0f + expf(-best));
            int pos = atomicAdd(&g_count[be], 1);
            g_dest [be * CAP + pos] = t * TOPK + k;
            g_gatew[be * CAP + pos] = gv;
        }
    }
}

// ---------------- kernel 2 (merged): all fp16 conversions ------------------
// grid (4096, 3): y=0 X, y=1 keys^T, y=2 values^T
__global__ void convert_kernel(const float* __restrict__ x,
                               const float* __restrict__ keys,
                               const float* __restrict__ values) {
    const int tid = threadIdx.x;
    if (blockIdx.y == 0) {
        size_t i = ((size_t)blockIdx.x * 256 + tid) * 8;
        float4 a = *(const float4*)(x + i), b = *(const float4*)(x + i + 4);
        uint4 o;
        o.x = pack_f16(a.x, a.y); o.y = pack_f16(a.z, a.w);
        o.z = pack_f16(b.x, b.y); o.w = pack_f16(b.z, b.w);
        *(uint4*)(g_xh + i) = o;
    } else if (blockIdx.y == 1) {
        __shared__ float tile[32][33];
        int bx = blockIdx.x, e = bx >> 7, rem = bx & 127;
        int d0 = (rem & 31) * 32, h0 = (rem >> 5) * 32;
        int tx = tid & 31, ty = tid >> 5;
        const float* src = keys + (size_t)e * DDIM * HDIM;
        #pragma unroll
        for (int i = 0; i < 4; i++)
            tile[ty + i * 8][tx] = src[(size_t)(d0 + ty + i * 8) * HDIM + h0 + tx];
        __syncthreads();
        #pragma unroll
        for (int i = 0; i < 4; i++)
            g_kth[((size_t)e * HDIM + h0 + ty + i * 8) * DDIM + d0 + tx] =
                __float2half(tile[tx][ty + i * 8]);
    } else {
        __shared__ float tile[32][33];
        int bx = blockIdx.x, e = bx >> 7, rem = bx & 127;
        int h0 = (rem & 3) * 32, d0 = (rem >> 2) * 32;
        int tx = tid & 31, ty = tid >> 5;
        const float* src = values + (size_t)e * HDIM * DDIM;
        #pragma unroll
        for (int i = 0; i < 4; i++)
            tile[ty + i * 8][tx] = src[(size_t)(h0 + ty + i * 8) * DDIM + d0 + tx];
        __syncthreads();
        #pragma unroll
        for (int i = 0; i < 4; i++)
            g_vth[((size_t)e * DDIM + d0 + ty + i * 8) * HDIM + h0 + tx] =
                __float2half(tile[tx][ty + i * 8]);
    }
}

// ---------------- kernel 3: grouped FFN, fp16 single pass ------------------
// smem (dynamic, 74752 B/CTA -> 2 CTA/SM):
//   0 s_dest[128] | 512 s_gate[128]
//   SM_ARENA = 1024:
//     GEMM1 stage s @ s*36864: A +0 | B +18432          (rows 144 B)
//     GEMM2 (after GEMM1 done): H @ +0 (34816, rows 272 B)
//            B2 stage s @ +36864 + s*17408 (rows 272 B)
#define SM_DEST  0
#define SM_GATE  512
#define SM_ARENA 1024
#define G1_STAGE 36864
#define G1_B     18432
#define B2_OFF   36864
#define B2_STAGE 17408
#define SM_TOTAL (1024 + 73728)

__global__ __launch_bounds__(256, 2) void moe_ffn_mma() {
    extern __shared__ char smc[];
    const uint32_t smb = smem_u32(smc);
    const int e = blockIdx.y;
    const int cnt = g_count[e];
    const int start = blockIdx.x * MT;
    if (start >= cnt) return;
    const int ntok = min(MT, cnt - start);

    const int tid = threadIdx.x, lane = tid & 31, wid = tid >> 5;
    const int m0 = (wid & 3) * 32;        // 4 warps in M
    const int n0 = (wid >> 2) * 64;       // 2 warps in N (GEMM1: 64 cols)
    const int n02 = (wid >> 2) * 32;      // GEMM2: 32 cols of 64-col chunk

    int*   s_dest = (int*)(smc + SM_DEST);
    float* s_gate = (float*)(smc + SM_GATE);
    if (tid < MT) {
        if (tid < ntok) {
            int idx = e * CAP + start + tid;
            s_dest[tid] = g_dest[idx];
            s_gate[tid] = g_gatew[idx];
        } else { s_dest[tid] = 0; s_gate[tid] = 0.f; }
    }
    __syncthreads();

    // staging geometry
    const int srow = tid >> 1, shf = tid & 1;           // GEMM1: 2 thr/row
    const bool svalid = srow < ntok;
    const size_t arowA = (size_t)(s_dest[srow] >> 2) * DDIM;
    const size_t browK = ((size_t)e * HDIM + srow) * DDIM;
    const int srow2 = tid >> 2, shf2 = tid & 3;         // GEMM2: 4 thr/row

    // ldmatrix lane address components
    const int rowo = (lane & 7) + ((lane >> 3) & 1) * 8;
    const int colx = (lane >> 4) * 8;

    auto stage1 = [&](int s, int kc) {
        uint32_t base = smb + SM_ARENA + s * G1_STAGE + (uint32_t)srow * 144 + shf * 64;
        size_t ko = (size_t)kc * 64 + shf * 32;
        #pragma unroll
        for (int j = 0; j < 4; j++) {
            cp16(base +        j * 16, g_xh  + arowA + ko + j * 8, svalid);
            cp16(base + G1_B + j * 16, g_kth + browK + ko + j * 8, true);
        }
    };
    auto stage2 = [&](int s, int nch) {
        size_t so = ((size_t)e * DDIM + nch * 64 + srow2) * HDIM + shf2 * 32;
        uint32_t base = smb + SM_ARENA + B2_OFF + s * B2_STAGE
                      + (uint32_t)srow2 * 272 + shf2 * 64;
        #pragma unroll
        for (int j = 0; j < 4; j++)
            cp16(base + j * 16, g_vth + so + j * 8, true);
    };

    float acc[2][8][4] = {};

    // ================= GEMM1: C1 = X @ keys^T ==============================
    stage1(0, 0);
    CP_COMMIT();
    for (int kc = 0; kc < DDIM / 64; kc++) {
        if (kc + 1 < DDIM / 64) stage1((kc + 1) & 1, kc + 1);
        CP_COMMIT();
        CP_WAIT1();
        __syncthreads();

        const uint32_t sb = smb + SM_ARENA + (kc & 1) * G1_STAGE;
        #pragma unroll
        for (int ks = 0; ks < 4; ks++) {
            const int kloc = ks * 16;
            uint32_t a[2][4], b[8][2];
            #pragma unroll
            for (int mt2 = 0; mt2 < 2; mt2++) {
                uint32_t ao = (uint32_t)(m0 + mt2 * 16 + rowo) * 144 + (kloc + colx) * 2;
                ldsm_x4(a[mt2], sb + ao);
            }
            #pragma unroll
            for (int p = 0; p < 4; p++) {   // each x4 covers 2 n-octets
                uint32_t bo = (uint32_t)(n0 + p * 16 + rowo) * 144 + (kloc + colx) * 2;
                uint32_t bq[4];
                ldsm_x4(bq, sb + G1_B + bo);
                b[2 * p][0] = bq[0]; b[2 * p][1] = bq[2];
                b[2 * p + 1][0] = bq[1]; b[2 * p + 1][1] = bq[3];
            }
            #pragma unroll
            for (int nt2 = 0; nt2 < 8; nt2++)
                #pragma unroll
                for (int mt2 = 0; mt2 < 2; mt2++)
                    mma_f16(acc[mt2][nt2], a[mt2], b[nt2]);
        }
        __syncthreads();
    }

    // prefetch first B2 tile (overlaps epilogue1 register math)
    stage2(0, 0);
    CP_COMMIT();

    // ================= epilogue1: H = relu(C1)*gate -> smem fp16 ===========
    #pragma unroll
    for (int mt2 = 0; mt2 < 2; mt2++) {
        int rA = m0 + mt2 * 16 + (lane >> 2);
        float gA = s_gate[rA], gB = s_gate[rA + 8];
        #pragma unroll
        for (int nt2 = 0; nt2 < 8; nt2++) {
            int col = n0 + nt2 * 8 + (lane & 3) * 2;
            float c0 = fmaxf(acc[mt2][nt2][0], 0.f) * gA;
            float c1 = fmaxf(acc[mt2][nt2][1], 0.f) * gA;
            float c2 = fmaxf(acc[mt2][nt2][2], 0.f) * gB;
            float c3 = fmaxf(acc[mt2][nt2][3], 0.f) * gB;
            *(uint32_t*)(smc + SM_ARENA + rA * 272 + col * 2)       = pack_f16(c0, c1);
            *(uint32_t*)(smc + SM_ARENA + (rA + 8) * 272 + col * 2) = pack_f16(c2, c3);
        }
    }

    // ================= GEMM2: out = H @ values^T, 16 chunks of 64 cols =====
    for (int nch = 0; nch < DDIM / 64; nch++) {
        if (nch + 1 < DDIM / 64) stage2((nch + 1) & 1, nch + 1);
        CP_COMMIT();
        CP_WAIT1();
        __syncthreads();

        const uint32_t hb = smb + SM_ARENA;
        const uint32_t b2 = smb + SM_ARENA + B2_OFF + (nch & 1) * B2_STAGE;
        float a2[2][4][4] = {};
        #pragma unroll
        for (int ks = 0; ks < 8; ks++) {
            const int kloc = ks * 16;
            uint32_t a[2][4], b[4][2];
            #pragma unroll
            for (int mt2 = 0; mt2 < 2; mt2++) {
                uint32_t ao = (uint32_t)(m0 + mt2 * 16 + rowo) * 272 + (kloc + colx) * 2;
                ldsm_x4(a[mt2], hb + ao);
            }
            #pragma unroll
            for (int p = 0; p < 2; p++) {
                uint32_t bo = (uint32_t)(n02 + p * 16 + rowo) * 272 + (kloc + colx) * 2;
                uint32_t bq[4];
                ldsm_x4(bq, b2 + bo);
                b[2 * p][0] = bq[0]; b[2 * p][1] = bq[2];
                b[2 * p + 1][0] = bq[1]; b[2 * p + 1][1] = bq[3];
            }
            #pragma unroll
            for (int nt2 = 0; nt2 < 4; nt2++)
                #pragma unroll
                for (int mt2 = 0; mt2 < 2; mt2++)
                    mma_f16(a2[mt2][nt2], a[mt2], b[nt2]);
        }

        // epilogue2: direct stores (4 consecutive lanes = one 32B sector)
        #pragma unroll
        for (int mt2 = 0; mt2 < 2; mt2++) {
            int rA = m0 + mt2 * 16 + (lane >> 2);
            #pragma unroll
            for (int nt2 = 0; nt2 < 4; nt2++) {
                int col = nch * 64 + n02 + nt2 * 8 + (lane & 3) * 2;
                if (rA < ntok) {
                    float2 v = make_float2(a2[mt2][nt2][0], a2[mt2][nt2][1]);
                    *(float2*)(g_partial + (size_t)s_dest[rA] * DDIM + col) = v;
                }
                if (rA + 8 < ntok) {
                    float2 v = make_float2(a2[mt2][nt2][2], a2[mt2][nt2][3]);
                    *(float2*)(g_partial + (size_t)s_dest[rA + 8] * DDIM + col) = v;
                }
            }
        }
        __syncthreads();
    }
}

// ---------------- kernel 4: gather 4 partial rows per token ----------------
__global__ void gather_kernel(float* __restrict__ out) {
    int i = blockIdx.x * blockDim.x + threadIdx.x;
    int n = i >> 8, c = i & 255;
    const float4* p = (const float4*)g_partial;
    size_t base = (size_t)n * 4 * 256 + c;
    float4 a = p[base], b = p[base + 256], d = p[base + 512], f = p[base + 768];
    float4 r;
    r.x = a.x + b.x + d.x + f.x; r.y = a.y + b.y + d.y + f.y;
    r.z = a.z + b.z + d.z + f.z; r.w = a.w + b.w + d.w + f.w;
    ((float4*)out)[i] = r;
}

// ---------------- launch ----------------------------------------------------
extern "C" void kernel_launch(void* const* d_in, const int* in_sizes, int n_in,
                              void* d_out, int out_size) {
    const float* x      = (const float*)d_in[0];
    const float* W      = (const float*)d_in[1];
    const float* keys   = (const float*)d_in[2];
    const float* values = (const float*)d_in[3];
    float* out = (float*)d_out;

    cudaFuncSetAttribute(moe_ffn_mma, cudaFuncAttributeMaxDynamicSharedMemorySize, SM_TOTAL);

    zero_counts_kernel<<<1, 32>>>();
    gate_topk_kernel<<<NTOK / 4, 128>>>(x, W);
    convert_kernel<<<dim3(4096, 3), 256>>>(x, keys, values);
    moe_ffn_mma<<<dim3(CAP / MT, NEXP), 256, SM_TOTAL>>>();
    gather_kernel<<<(NTOK * DDIM / 4) / 256, 256>>>(out);
}